// round 12
// baseline (speedup 1.0000x reference)
#include <cuda_runtime.h>

#define NB 4096
#define ND 32
#define NK 64
#define NHID 128
#define ALPHA 0.2f
#define NEGV (-9e15f)
#define OBSW 3584

// ---- gat_main smem layout (float offsets) ---- (R8-identical)
#define OFF_ADJ   0        // 2048  dead after attn
#define OFF_CT    2048     // 2112  dead after h_drone
#define CTLD 132
#define OFF_RT    0        // 4096  written in r-GEMM (over ADJ+CT)
#define RTLD 32
#define OFF_DOCKT 4160     // 1088  live until h_dock
#define DKTLD 68
#define OFF_HDT   5248     // 4608  (Wdk heads 0-1 prefetch early; HDT written end of h_drone)
#define HDTLD 36
#define OFF_HKT   5248     // 8192  written in h_dock (over HDT)
#define HKTLD 64
#define OFF_SRC   9856     // 128
#define OFF_DST   9984     // 256
#define OFF_VS    10240    // 64
#define OFF_VD    10304    // 64
#define OFF_ATTN  10368    // 1024 (128 per warp: 2 rows)
#define OFF_DRONE 11392    // 512
#define OFF_U     13440    // 128
#define OFF_VB    13568    // 128
#define OFF_T     13696    // 32
#define SMF       13728    // 54912 B -> 4 CTAs/SM

typedef unsigned long long u64;
typedef unsigned int u32;

__device__ __forceinline__ u64 pk2(float lo, float hi) {
    u64 r; asm("mov.b64 %0,{%1,%2};" : "=l"(r) : "f"(lo), "f"(hi)); return r;
}
__device__ __forceinline__ void fma2(u64& d, u64 a, u64 b) {
    asm("fma.rn.f32x2 %0, %1, %2, %0;" : "+l"(d) : "l"(a), "l"(b));
}
__device__ __forceinline__ float2 up2(u64 v) {
    float2 f; asm("mov.b64 {%0,%1},%2;" : "=f"(f.x), "=f"(f.y) : "l"(v)); return f;
}

__device__ float g_hd[(size_t)NB * ND * NHID];   // 64 MB
__device__ float g_hpart[8ull * NB * 64];        // 8 MB critic partials
__device__ float g_Wc1t[64 * 4096];              // 1 MB transposed Wc1
__device__ float g_M[NHID * NHID];
__device__ float g_vb[NHID];
__device__ float g_u[NHID];
__device__ float g_s0[1];
__device__ float g_vsrc[64];
__device__ float g_vdst[64];
__device__ float g_wbar[16 * NHID];

__device__ __forceinline__ float eluf(float x) { return x > 0.f ? x : expm1f(x); }

// ================= precompute (batch-independent), grid=17 =================
__global__ void precomp(const float* __restrict__ Wdr, const float* __restrict__ Wdk,
                        const float* __restrict__ asrc, const float* __restrict__ adst,
                        const float* __restrict__ Wad, const float* __restrict__ Wak,
                        const float* __restrict__ bad, const float* __restrict__ bak)
{
    const int t = threadIdx.x;
    if (blockIdx.x < 16) {
        __shared__ float swad[8 * 128];
        __shared__ float swak[32 * 128];
        const int a0 = blockIdx.x * 8;
        for (int i = t; i < 1024; i += 256) swad[i] = Wad[a0 * 128 + i];
        for (int jb = 0; jb < 4; jb++) {
            __syncthreads();
            for (int i = t; i < 4096; i += 256) swak[i] = Wak[jb * 4096 + i];
            __syncthreads();
            const int aa = t >> 5, jl = t & 31;
            float s = 0.f;
            for (int c = 0; c < 128; c++) {
                int cc = (c + jl) & 127;
                s += swad[aa * 128 + cc] * swak[jl * 128 + cc];
            }
            g_M[(a0 + aa) * 128 + jb * 32 + jl] = s;
        }
        if (t < 8) {
            float s = 0.f;
            for (int c = 0; c < 128; c++) s += swad[t * 128 + c] * bak[c];
            g_u[a0 + t] = s;
        }
    } else {
        __shared__ float sb[128];
        if (t < 128) sb[t] = bad[t];
        __syncthreads();
        if (t < 128) {
            float s = 0.f;
            for (int c = 0; c < 128; c++) s += sb[c] * Wak[t * 128 + c];
            g_vb[t] = s;
        }
        if (t == 0) {
            float s = 0.f;
            for (int c = 0; c < 128; c++) s += sb[c] * bak[c];
            g_s0[0] = s;
        }
        if (t < 64) {
            int h = t >> 4, f = t & 15;
            float s = 0.f;
            for (int c = 0; c < 128; c++) s += Wdr[(h * 16 + f) * 128 + c] * asrc[h * 128 + c];
            g_vsrc[t] = s;
        } else if (t < 128) {
            int u2 = t - 64, h = u2 >> 4, f = u2 & 15;
            float s = 0.f;
            for (int c = 0; c < 128; c++) s += Wdk[(h * 16 + f) * 128 + c] * adst[h * 128 + c];
            g_vdst[u2] = s;
        }
        for (int i = t; i < 2048; i += 256) {
            float s = Wdk[i] + Wdk[2048 + i] + Wdk[4096 + i] + Wdk[6144 + i];
            g_wbar[i] = s * 0.25f;
        }
    }
}

// ================= Wc1 transpose: g_Wc1t[j][k] = Wc1[k][j] =================
__global__ void __launch_bounds__(256) transpose_wc1(const float* __restrict__ Wc1)
{
    __shared__ float tile[64][65];
    const int k0 = blockIdx.x * 64;
    const int t = threadIdx.x;
    for (int i = t; i < 4096; i += 256) {
        int kk = i >> 6, j = i & 63;
        tile[kk][j] = Wc1[(size_t)(k0 + kk) * 64 + j];
    }
    __syncthreads();
    for (int i = t; i < 4096; i += 256) {
        int j = i >> 6, kk = i & 63;
        g_Wc1t[(size_t)j * 4096 + k0 + kk] = tile[kk][j];
    }
}

// ================= per-batch kernel (R8 + cp.async Wdk prefetch) =================
__global__ void __launch_bounds__(256, 4) gat_main(
    const float* __restrict__ obs, const float* __restrict__ Wdk,
    float* __restrict__ out_logits)
{
    extern __shared__ float sm[];
    const int b = blockIdx.x, t = threadIdx.x;
    const int w = t >> 5, lane = t & 31;
    const int k4 = lane * 4;
    const float* rowp = obs + (size_t)b * OBSW;

    // ---- 0. prefetch Wdk heads 0-1 (4096 floats) into dead HDT region via cp.async ----
    {
        #pragma unroll
        for (int q = 0; q < 4; q++) {
            int idx = (t + q * 256) * 4;
            u32 saddr = (u32)__cvta_generic_to_shared(&sm[OFF_HDT + idx]);
            asm volatile("cp.async.ca.shared.global [%0], [%1], 16;"
                         :: "r"(saddr), "l"(Wdk + idx));
        }
        asm volatile("cp.async.commit_group;");
    }

    // ---- 1. load per-batch data ----
    for (int i = t; i < 512;  i += 256) sm[OFF_DRONE + i] = rowp[i];
    for (int i = t; i < 1024; i += 256) {
        int m = i >> 4, f = i & 15;
        sm[OFF_DOCKT + f * DKTLD + m] = rowp[512 + i];
    }
    for (int i = t; i < 2048; i += 256) sm[OFF_ADJ + i] = rowp[1536 + i];
    if (t < 64)       sm[OFF_VS + t]       = g_vsrc[t];
    else if (t < 128) sm[OFF_VD + t - 64]  = g_vdst[t - 64];
    else              sm[OFF_VB + t - 128] = g_vb[t - 128];
    for (int i = t; i < 128; i += 256) sm[OFF_U + i] = g_u[i];
    __syncthreads();

    // ---- 2. src[h,n], dst[h,m] ----
    if (t < 128) {
        int h = t >> 5, n = t & 31;
        float s = 0.f;
        #pragma unroll
        for (int f = 0; f < 16; f++) s += sm[OFF_DRONE + n * 16 + f] * sm[OFF_VS + h * 16 + f];
        sm[OFF_SRC + t] = s;
    }
    {
        int h = t >> 6, m = t & 63;
        float s = 0.f;
        #pragma unroll
        for (int f = 0; f < 16; f++) s += sm[OFF_DOCKT + f * DKTLD + m] * sm[OFF_VD + h * 16 + f];
        sm[OFF_DST + h * 64 + m] = s;
    }
    __syncthreads();

    // ---- 3. attention: paired rows, softmax + cT[f][r] ----
    {
        const int h = w >> 1;
        const int fl = lane & 15, mb = (lane >> 4) * 32;
        const float d0 = sm[OFF_DST + h * 64 + lane];
        const float d1 = sm[OFF_DST + h * 64 + 32 + lane];
        for (int rp = 0; rp < 8; rp++) {
            const int r0 = w * 16 + rp * 2, r1 = r0 + 1;
            const int n0 = r0 & 31, n1 = r1 & 31;
            float sc0 = sm[OFF_SRC + h * 32 + n0];
            float sc1 = sm[OFF_SRC + h * 32 + n1];
            float e00 = sc0 + d0, e01 = sc0 + d1, e10 = sc1 + d0, e11 = sc1 + d1;
            e00 = e00 > 0.f ? e00 : ALPHA * e00;
            e01 = e01 > 0.f ? e01 : ALPHA * e01;
            e10 = e10 > 0.f ? e10 : ALPHA * e10;
            e11 = e11 > 0.f ? e11 : ALPHA * e11;
            if (!(sm[OFF_ADJ + n0 * 64 + lane] > 0.f))      e00 = NEGV;
            if (!(sm[OFF_ADJ + n0 * 64 + 32 + lane] > 0.f)) e01 = NEGV;
            if (!(sm[OFF_ADJ + n1 * 64 + lane] > 0.f))      e10 = NEGV;
            if (!(sm[OFF_ADJ + n1 * 64 + 32 + lane] > 0.f)) e11 = NEGV;
            float mx0 = fmaxf(e00, e01), mx1 = fmaxf(e10, e11);
            #pragma unroll
            for (int o = 16; o; o >>= 1) {
                mx0 = fmaxf(mx0, __shfl_xor_sync(~0u, mx0, o));
                mx1 = fmaxf(mx1, __shfl_xor_sync(~0u, mx1, o));
            }
            float p00 = __expf(e00 - mx0), p01 = __expf(e01 - mx0);
            float p10 = __expf(e10 - mx1), p11 = __expf(e11 - mx1);
            float su0 = p00 + p01, su1 = p10 + p11;
            #pragma unroll
            for (int o = 16; o; o >>= 1) {
                su0 += __shfl_xor_sync(~0u, su0, o);
                su1 += __shfl_xor_sync(~0u, su1, o);
            }
            float iv0 = 1.0f / su0, iv1 = 1.0f / su1;
            sm[OFF_ATTN + w * 128 + lane]       = p00 * iv0;
            sm[OFF_ATTN + w * 128 + 32 + lane]  = p01 * iv0;
            sm[OFF_ATTN + w * 128 + 64 + lane]  = p10 * iv1;
            sm[OFF_ATTN + w * 128 + 96 + lane]  = p11 * iv1;
            __syncwarp();
            float cc0 = 0.f, cc1 = 0.f;
            #pragma unroll
            for (int mm = 0; mm < 32; mm += 4) {
                float4 dv  = *(float4*)&sm[OFF_DOCKT + fl * DKTLD + mb + mm];
                float4 av0 = *(float4*)&sm[OFF_ATTN + w * 128 + mb + mm];
                float4 av1 = *(float4*)&sm[OFF_ATTN + w * 128 + 64 + mb + mm];
                cc0 += av0.x * dv.x + av0.y * dv.y + av0.z * dv.z + av0.w * dv.w;
                cc1 += av1.x * dv.x + av1.y * dv.y + av1.z * dv.z + av1.w * dv.w;
            }
            cc0 += __shfl_xor_sync(~0u, cc0, 16);
            cc1 += __shfl_xor_sync(~0u, cc1, 16);
            if (lane < 16) {
                sm[OFF_CT + fl * CTLD + r0] = cc0;
                sm[OFF_CT + fl * CTLD + r1] = cc1;
            }
            __syncwarp();
        }
    }
    asm volatile("cp.async.wait_group 0;");
    __syncthreads();

    // ---- 4. h_drone (FFMA2): heads 0-1 from smem stage, heads 2-3 from gmem ----
    u64 hacc2[8] = {};
    #pragma unroll 4
    for (int hf = 0; hf < 32; hf++) {
        ulonglong2 wv = *(ulonglong2*)&sm[OFF_HDT + hf * 128 + k4];
        float4 cv = *(float4*)&sm[OFF_CT + (hf & 15) * CTLD + (hf >> 4) * 32 + w * 4];
        u64 c0 = pk2(cv.x, cv.x), c1 = pk2(cv.y, cv.y);
        u64 c2 = pk2(cv.z, cv.z), c3 = pk2(cv.w, cv.w);
        fma2(hacc2[0], c0, wv.x); fma2(hacc2[1], c0, wv.y);
        fma2(hacc2[2], c1, wv.x); fma2(hacc2[3], c1, wv.y);
        fma2(hacc2[4], c2, wv.x); fma2(hacc2[5], c2, wv.y);
        fma2(hacc2[6], c3, wv.x); fma2(hacc2[7], c3, wv.y);
    }
    #pragma unroll 4
    for (int hf = 32; hf < 64; hf++) {
        ulonglong2 wv = *(const ulonglong2*)&Wdk[hf * 128 + k4];
        float4 cv = *(float4*)&sm[OFF_CT + (hf & 15) * CTLD + (hf >> 4) * 32 + w * 4];
        u64 c0 = pk2(cv.x, cv.x), c1 = pk2(cv.y, cv.y);
        u64 c2 = pk2(cv.z, cv.z), c3 = pk2(cv.w, cv.w);
        fma2(hacc2[0], c0, wv.x); fma2(hacc2[1], c0, wv.y);
        fma2(hacc2[2], c1, wv.x); fma2(hacc2[3], c1, wv.y);
        fma2(hacc2[4], c2, wv.x); fma2(hacc2[5], c2, wv.y);
        fma2(hacc2[6], c3, wv.x); fma2(hacc2[7], c3, wv.y);
    }
    __syncthreads();   // all smem-staged Wdk reads done before HDT overwrite below
    {
        float4 ho[4];
        #pragma unroll
        for (int i = 0; i < 4; i++) {
            float2 lo = up2(hacc2[2 * i]), hi = up2(hacc2[2 * i + 1]);
            ho[i].x = eluf(lo.x * 0.25f); ho[i].y = eluf(lo.y * 0.25f);
            ho[i].z = eluf(hi.x * 0.25f); ho[i].w = eluf(hi.y * 0.25f);
            *(float4*)&g_hd[((size_t)b * ND + w * 4 + i) * 128 + k4] = ho[i];
        }
        float4 u4 = *(float4*)&sm[OFF_U + k4];
        float pt[4];
        #pragma unroll
        for (int i = 0; i < 4; i++)
            pt[i] = ho[i].x * u4.x + ho[i].y * u4.y + ho[i].z * u4.z + ho[i].w * u4.w;
        #pragma unroll
        for (int i = 0; i < 4; i++)
            #pragma unroll
            for (int o = 16; o; o >>= 1) pt[i] += __shfl_xor_sync(~0u, pt[i], o);
        if (lane == 0) {
            float s0v = g_s0[0];
            #pragma unroll
            for (int i = 0; i < 4; i++) sm[OFF_T + w * 4 + i] = pt[i] + s0v;
        }
        *(float4*)&sm[OFF_HDT + (k4 + 0) * HDTLD + w * 4] = make_float4(ho[0].x, ho[1].x, ho[2].x, ho[3].x);
        *(float4*)&sm[OFF_HDT + (k4 + 1) * HDTLD + w * 4] = make_float4(ho[0].y, ho[1].y, ho[2].y, ho[3].y);
        *(float4*)&sm[OFF_HDT + (k4 + 2) * HDTLD + w * 4] = make_float4(ho[0].z, ho[1].z, ho[2].z, ho[3].z);
        *(float4*)&sm[OFF_HDT + (k4 + 3) * HDTLD + w * 4] = make_float4(ho[0].w, ho[1].w, ho[2].w, ho[3].w);
    }
    __syncthreads();

    // ---- 5. r = hd @ M + vb (FFMA2, M from gmem/L2): tile 2n x 8j -> rT[j][n] ----
    {
        const int n0 = (t & 15) * 2, j0 = (t >> 4) * 8;
        u64 acc2[2][4] = {};
        #pragma unroll 8
        for (int al = 0; al < 128; al++) {
            ulonglong2 m01 = *(const ulonglong2*)&g_M[al * 128 + j0];
            ulonglong2 m23 = *(const ulonglong2*)&g_M[al * 128 + j0 + 4];
            float2 hv = *(float2*)&sm[OFF_HDT + al * HDTLD + n0];
            u64 h0 = pk2(hv.x, hv.x), h1 = pk2(hv.y, hv.y);
            fma2(acc2[0][0], h0, m01.x); fma2(acc2[0][1], h0, m01.y);
            fma2(acc2[0][2], h0, m23.x); fma2(acc2[0][3], h0, m23.y);
            fma2(acc2[1][0], h1, m01.x); fma2(acc2[1][1], h1, m01.y);
            fma2(acc2[1][2], h1, m23.x); fma2(acc2[1][3], h1, m23.y);
        }
        __syncthreads();   // HDT reads done everywhere; RT region (over ADJ/CT) now writable
        #pragma unroll
        for (int jp = 0; jp < 4; jp++) {
            float2 a0 = up2(acc2[0][jp]);
            float2 a1 = up2(acc2[1][jp]);
            float vb0 = sm[OFF_VB + j0 + 2 * jp], vb1 = sm[OFF_VB + j0 + 2 * jp + 1];
            *(float2*)&sm[OFF_RT + (j0 + 2 * jp) * RTLD + n0]     = make_float2(a0.x + vb0, a1.x + vb0);
            *(float2*)&sm[OFF_RT + (j0 + 2 * jp + 1) * RTLD + n0] = make_float2(a0.y + vb1, a1.y + vb1);
        }
    }
    __syncthreads();

    // ---- 6. h_dock (FFMA2, wbar from gmem): tile 8m x 4k -> hkT[k][m] (over HDT) ----
    {
        const int m0 = (t & 7) * 8, k0 = (t >> 3) * 4;
        u64 acc2[8][2] = {};
        #pragma unroll
        for (int f = 0; f < 16; f++) {
            ulonglong2 wv = *(const ulonglong2*)&g_wbar[f * 128 + k0];
            float4 da = *(float4*)&sm[OFF_DOCKT + f * DKTLD + m0];
            float4 db = *(float4*)&sm[OFF_DOCKT + f * DKTLD + m0 + 4];
            u64 d0 = pk2(da.x, da.x), d1 = pk2(da.y, da.y), d2 = pk2(da.z, da.z), d3 = pk2(da.w, da.w);
            u64 d4 = pk2(db.x, db.x), d5 = pk2(db.y, db.y), d6 = pk2(db.z, db.z), d7 = pk2(db.w, db.w);
            fma2(acc2[0][0], d0, wv.x); fma2(acc2[0][1], d0, wv.y);
            fma2(acc2[1][0], d1, wv.x); fma2(acc2[1][1], d1, wv.y);
            fma2(acc2[2][0], d2, wv.x); fma2(acc2[2][1], d2, wv.y);
            fma2(acc2[3][0], d3, wv.x); fma2(acc2[3][1], d3, wv.y);
            fma2(acc2[4][0], d4, wv.x); fma2(acc2[4][1], d4, wv.y);
            fma2(acc2[5][0], d5, wv.x); fma2(acc2[5][1], d5, wv.y);
            fma2(acc2[6][0], d6, wv.x); fma2(acc2[6][1], d6, wv.y);
            fma2(acc2[7][0], d7, wv.x); fma2(acc2[7][1], d7, wv.y);
        }
        float accf[8][4];
        #pragma unroll
        for (int m = 0; m < 8; m++) {
            float2 a = up2(acc2[m][0]), bq = up2(acc2[m][1]);
            accf[m][0] = a.x; accf[m][1] = a.y; accf[m][2] = bq.x; accf[m][3] = bq.y;
        }
        #pragma unroll
        for (int q = 0; q < 4; q++) {
            float4 va = make_float4(eluf(accf[0][q]), eluf(accf[1][q]), eluf(accf[2][q]), eluf(accf[3][q]));
            float4 vb4 = make_float4(eluf(accf[4][q]), eluf(accf[5][q]), eluf(accf[6][q]), eluf(accf[7][q]));
            *(float4*)&sm[OFF_HKT + (k0 + q) * HKTLD + m0] = va;
            *(float4*)&sm[OFF_HKT + (k0 + q) * HKTLD + m0 + 4] = vb4;
        }
    }
    __syncthreads();

    // ---- 7. logits (FFMA2): tile 2n x 4m, adj from gmem ----
    {
        const int n0 = (t >> 4) * 2, m0 = (t & 15) * 4;
        const float* adjp = rowp + 1536;
        float4 j0v = *(const float4*)&adjp[n0 * 64 + m0];
        float4 j1v = *(const float4*)&adjp[(n0 + 1) * 64 + m0];
        u64 acc2[2][2] = {};
        #pragma unroll 4
        for (int j = 0; j < 128; j++) {
            float2 rv = *(float2*)&sm[OFF_RT + j * RTLD + n0];
            ulonglong2 hv = *(ulonglong2*)&sm[OFF_HKT + j * HKTLD + m0];
            u64 r0 = pk2(rv.x, rv.x), r1 = pk2(rv.y, rv.y);
            fma2(acc2[0][0], r0, hv.x); fma2(acc2[0][1], r0, hv.y);
            fma2(acc2[1][0], r1, hv.x); fma2(acc2[1][1], r1, hv.y);
        }
        float2 p00 = up2(acc2[0][0]), p01 = up2(acc2[0][1]);
        float2 p10 = up2(acc2[1][0]), p11 = up2(acc2[1][1]);
        float t0 = sm[OFF_T + n0], t1 = sm[OFF_T + n0 + 1];
        float4 o0, o1;
        o0.x = j0v.x > 0.f ? p00.x + t0 : NEGV; o0.y = j0v.y > 0.f ? p00.y + t0 : NEGV;
        o0.z = j0v.z > 0.f ? p01.x + t0 : NEGV; o0.w = j0v.w > 0.f ? p01.y + t0 : NEGV;
        o1.x = j1v.x > 0.f ? p10.x + t1 : NEGV; o1.y = j1v.y > 0.f ? p10.y + t1 : NEGV;
        o1.z = j1v.z > 0.f ? p11.x + t1 : NEGV; o1.w = j1v.w > 0.f ? p11.y + t1 : NEGV;
        float* op = out_logits + (size_t)b * 2048;
        *(float4*)&op[n0 * 64 + m0] = o0;
        *(float4*)&op[(n0 + 1) * 64 + m0] = o1;
    }
}

// ================= critic: split-K(8) GEMM then combine =================
__global__ void __launch_bounds__(256) critic_gemm()
{
    __shared__ float s_chunk[32 * 128];
    const int t = threadIdx.x;
    const int b0 = blockIdx.x * 32;
    const int kb = blockIdx.y * 512;
    const int j = t & 63, rg = t >> 6;
    float acc[8] = {};

    for (int c = 0; c < 4; c++) {
        const int kbase = kb + c * 128;
        __syncthreads();
        for (int idx = t; idx < 1024; idx += 256) {
            int r = idx >> 5, c4 = (idx & 31) * 4;
            *(float4*)&s_chunk[r * 128 + c4] =
                *(const float4*)&g_hd[(size_t)(b0 + r) * 4096 + kbase + c4];
        }
        __syncthreads();
        const float* wrow = &g_Wc1t[(size_t)j * 4096 + kbase];
        for (int ii = 0; ii < 128; ii += 4) {
            float4 wv = *(const float4*)&wrow[ii];
            #pragma unroll
            for (int r = 0; r < 8; r++) {
                float4 h4 = *(const float4*)&s_chunk[(rg * 8 + r) * 128 + ii];
                acc[r] += h4.x * wv.x + h4.y * wv.y + h4.z * wv.z + h4.w * wv.w;
            }
        }
    }
    #pragma unroll
    for (int r = 0; r < 8; r++)
        g_hpart[((size_t)blockIdx.y * NB + b0 + rg * 8 + r) * 64 + j] = acc[r];
}

__global__ void __launch_bounds__(256) critic_final(
    const float* __restrict__ bc1, const float* __restrict__ Wc2,
    const float* __restrict__ bc2, float* __restrict__ out_values)
{
    const int w = threadIdx.x >> 5, lane = threadIdx.x & 31;
    const int b = blockIdx.x * 8 + w;
    float a = 0.f;
    #pragma unroll
    for (int half = 0; half < 2; half++) {
        int jj = lane + 32 * half;
        size_t o = (size_t)b * 64 + jj;
        float h = bc1[jj];
        #pragma unroll
        for (int p = 0; p < 8; p++) h += g_hpart[(size_t)p * NB * 64 + o];
        a += (h > 0.f ? h : 0.f) * Wc2[jj];
    }
    #pragma unroll
    for (int o = 16; o; o >>= 1) a += __shfl_xor_sync(~0u, a, o);
    if (lane == 0) out_values[b] = a + bc2[0];
}

extern "C" void kernel_launch(void* const* d_in, const int* in_sizes, int n_in,
                              void* d_out, int out_size)
{
    const float* obs  = (const float*)d_in[0];
    const float* Wdr  = (const float*)d_in[1];
    const float* Wdk  = (const float*)d_in[2];
    const float* asrc = (const float*)d_in[3];
    const float* adst = (const float*)d_in[4];
    const float* Wc1  = (const float*)d_in[5];
    const float* bc1  = (const float*)d_in[6];
    const float* Wc2  = (const float*)d_in[7];
    const float* bc2  = (const float*)d_in[8];
    const float* Wad  = (const float*)d_in[9];
    const float* bad  = (const float*)d_in[10];
    const float* Wak  = (const float*)d_in[11];
    const float* bak  = (const float*)d_in[12];

    float* out        = (float*)d_out;
    float* out_values = out;
    float* out_logits = out + NB;

    cudaFuncSetAttribute(gat_main, cudaFuncAttributeMaxDynamicSharedMemorySize,
                         SMF * (int)sizeof(float));

    precomp<<<17, 256>>>(Wdr, Wdk, asrc, adst, Wad, Wak, bad, bak);
    transpose_wc1<<<64, 256>>>(Wc1);
    gat_main<<<NB, 256, SMF * sizeof(float)>>>(obs, Wdk, out_logits);
    critic_gemm<<<dim3(NB / 32, 8), 256>>>();
    critic_final<<<NB / 8, 256>>>(bc1, Wc2, bc2, out_values);
}

// round 13
// speedup vs baseline: 1.0956x; 1.0956x over previous
#include <cuda_runtime.h>

#define NB 4096
#define ND 32
#define NK 64
#define NHID 128
#define ALPHA 0.2f
#define NEGV (-9e15f)
#define OBSW 3584

// ---- gat_main smem layout (float offsets) ---- (R8-identical)
#define OFF_ADJ   0
#define OFF_CT    2048
#define CTLD 132
#define OFF_RT    0
#define RTLD 32
#define OFF_DOCKT 4160
#define DKTLD 68
#define OFF_HDT   5248
#define HDTLD 36
#define OFF_HKT   5248
#define HKTLD 64
#define OFF_SRC   9856
#define OFF_DST   9984
#define OFF_VS    10240
#define OFF_VD    10304
#define OFF_ATTN  10368
#define OFF_DRONE 11392
#define OFF_U     13440
#define OFF_VB    13568
#define OFF_T     13696
#define SMF       13728    // 54912 B -> 4 CTAs/SM

typedef unsigned long long u64;
typedef unsigned int u32;

__device__ __forceinline__ u64 pk2(float lo, float hi) {
    u64 r; asm("mov.b64 %0,{%1,%2};" : "=l"(r) : "f"(lo), "f"(hi)); return r;
}
__device__ __forceinline__ void fma2(u64& d, u64 a, u64 b) {
    asm("fma.rn.f32x2 %0, %1, %2, %0;" : "+l"(d) : "l"(a), "l"(b));
}
__device__ __forceinline__ float2 up2(u64 v) {
    float2 f; asm("mov.b64 {%0,%1},%2;" : "=f"(f.x), "=f"(f.y) : "l"(v)); return f;
}

__device__ float g_hd[(size_t)NB * ND * NHID];   // 64 MB
__device__ float g_hpart[8ull * NB * 64];        // 8 MB critic partials
__device__ float g_M[NHID * NHID];
__device__ float g_vb[NHID];
__device__ float g_u[NHID];
__device__ float g_s0[1];
__device__ float g_vsrc[64];
__device__ float g_vdst[64];
__device__ float g_wbar[16 * NHID];

__device__ __forceinline__ float eluf(float x) { return x > 0.f ? x : expm1f(x); }

// ================= precompute (batch-independent), grid=17 =================
__global__ void precomp(const float* __restrict__ Wdr, const float* __restrict__ Wdk,
                        const float* __restrict__ asrc, const float* __restrict__ adst,
                        const float* __restrict__ Wad, const float* __restrict__ Wak,
                        const float* __restrict__ bad, const float* __restrict__ bak)
{
    const int t = threadIdx.x;
    if (blockIdx.x < 16) {
        __shared__ float swad[8 * 128];
        __shared__ float swak[32 * 128];
        const int a0 = blockIdx.x * 8;
        for (int i = t; i < 1024; i += 256) swad[i] = Wad[a0 * 128 + i];
        for (int jb = 0; jb < 4; jb++) {
            __syncthreads();
            for (int i = t; i < 4096; i += 256) swak[i] = Wak[jb * 4096 + i];
            __syncthreads();
            const int aa = t >> 5, jl = t & 31;
            float s = 0.f;
            for (int c = 0; c < 128; c++) {
                int cc = (c + jl) & 127;
                s += swad[aa * 128 + cc] * swak[jl * 128 + cc];
            }
            g_M[(a0 + aa) * 128 + jb * 32 + jl] = s;
        }
        if (t < 8) {
            float s = 0.f;
            for (int c = 0; c < 128; c++) s += swad[t * 128 + c] * bak[c];
            g_u[a0 + t] = s;
        }
    } else {
        __shared__ float sb[128];
        if (t < 128) sb[t] = bad[t];
        __syncthreads();
        if (t < 128) {
            float s = 0.f;
            for (int c = 0; c < 128; c++) s += sb[c] * Wak[t * 128 + c];
            g_vb[t] = s;
        }
        if (t == 0) {
            float s = 0.f;
            for (int c = 0; c < 128; c++) s += sb[c] * bak[c];
            g_s0[0] = s;
        }
        if (t < 64) {
            int h = t >> 4, f = t & 15;
            float s = 0.f;
            for (int c = 0; c < 128; c++) s += Wdr[(h * 16 + f) * 128 + c] * asrc[h * 128 + c];
            g_vsrc[t] = s;
        } else if (t < 128) {
            int u2 = t - 64, h = u2 >> 4, f = u2 & 15;
            float s = 0.f;
            for (int c = 0; c < 128; c++) s += Wdk[(h * 16 + f) * 128 + c] * adst[h * 128 + c];
            g_vdst[u2] = s;
        }
        for (int i = t; i < 2048; i += 256) {
            float s = Wdk[i] + Wdk[2048 + i] + Wdk[4096 + i] + Wdk[6144 + i];
            g_wbar[i] = s * 0.25f;
        }
    }
}

// ================= per-batch kernel (R8-identical) =================
__global__ void __launch_bounds__(256, 4) gat_main(
    const float* __restrict__ obs, const float* __restrict__ Wdk,
    float* __restrict__ out_logits)
{
    extern __shared__ float sm[];
    const int b = blockIdx.x, t = threadIdx.x;
    const int w = t >> 5, lane = t & 31;
    const int k4 = lane * 4;
    const float* rowp = obs + (size_t)b * OBSW;

    // ---- 1. load per-batch data ----
    for (int i = t; i < 512;  i += 256) sm[OFF_DRONE + i] = rowp[i];
    for (int i = t; i < 1024; i += 256) {
        int m = i >> 4, f = i & 15;
        sm[OFF_DOCKT + f * DKTLD + m] = rowp[512 + i];
    }
    for (int i = t; i < 2048; i += 256) sm[OFF_ADJ + i] = rowp[1536 + i];
    if (t < 64)       sm[OFF_VS + t]       = g_vsrc[t];
    else if (t < 128) sm[OFF_VD + t - 64]  = g_vdst[t - 64];
    else              sm[OFF_VB + t - 128] = g_vb[t - 128];
    for (int i = t; i < 128; i += 256) sm[OFF_U + i] = g_u[i];
    __syncthreads();

    // ---- 2. src[h,n], dst[h,m] ----
    if (t < 128) {
        int h = t >> 5, n = t & 31;
        float s = 0.f;
        #pragma unroll
        for (int f = 0; f < 16; f++) s += sm[OFF_DRONE + n * 16 + f] * sm[OFF_VS + h * 16 + f];
        sm[OFF_SRC + t] = s;
    }
    {
        int h = t >> 6, m = t & 63;
        float s = 0.f;
        #pragma unroll
        for (int f = 0; f < 16; f++) s += sm[OFF_DOCKT + f * DKTLD + m] * sm[OFF_VD + h * 16 + f];
        sm[OFF_DST + h * 64 + m] = s;
    }
    __syncthreads();

    // ---- 3. attention: paired rows, softmax + cT[f][r] ----
    {
        const int h = w >> 1;
        const int fl = lane & 15, mb = (lane >> 4) * 32;
        const float d0 = sm[OFF_DST + h * 64 + lane];
        const float d1 = sm[OFF_DST + h * 64 + 32 + lane];
        for (int rp = 0; rp < 8; rp++) {
            const int r0 = w * 16 + rp * 2, r1 = r0 + 1;
            const int n0 = r0 & 31, n1 = r1 & 31;
            float sc0 = sm[OFF_SRC + h * 32 + n0];
            float sc1 = sm[OFF_SRC + h * 32 + n1];
            float e00 = sc0 + d0, e01 = sc0 + d1, e10 = sc1 + d0, e11 = sc1 + d1;
            e00 = e00 > 0.f ? e00 : ALPHA * e00;
            e01 = e01 > 0.f ? e01 : ALPHA * e01;
            e10 = e10 > 0.f ? e10 : ALPHA * e10;
            e11 = e11 > 0.f ? e11 : ALPHA * e11;
            if (!(sm[OFF_ADJ + n0 * 64 + lane] > 0.f))      e00 = NEGV;
            if (!(sm[OFF_ADJ + n0 * 64 + 32 + lane] > 0.f)) e01 = NEGV;
            if (!(sm[OFF_ADJ + n1 * 64 + lane] > 0.f))      e10 = NEGV;
            if (!(sm[OFF_ADJ + n1 * 64 + 32 + lane] > 0.f)) e11 = NEGV;
            float mx0 = fmaxf(e00, e01), mx1 = fmaxf(e10, e11);
            #pragma unroll
            for (int o = 16; o; o >>= 1) {
                mx0 = fmaxf(mx0, __shfl_xor_sync(~0u, mx0, o));
                mx1 = fmaxf(mx1, __shfl_xor_sync(~0u, mx1, o));
            }
            float p00 = __expf(e00 - mx0), p01 = __expf(e01 - mx0);
            float p10 = __expf(e10 - mx1), p11 = __expf(e11 - mx1);
            float su0 = p00 + p01, su1 = p10 + p11;
            #pragma unroll
            for (int o = 16; o; o >>= 1) {
                su0 += __shfl_xor_sync(~0u, su0, o);
                su1 += __shfl_xor_sync(~0u, su1, o);
            }
            float iv0 = 1.0f / su0, iv1 = 1.0f / su1;
            sm[OFF_ATTN + w * 128 + lane]       = p00 * iv0;
            sm[OFF_ATTN + w * 128 + 32 + lane]  = p01 * iv0;
            sm[OFF_ATTN + w * 128 + 64 + lane]  = p10 * iv1;
            sm[OFF_ATTN + w * 128 + 96 + lane]  = p11 * iv1;
            __syncwarp();
            float cc0 = 0.f, cc1 = 0.f;
            #pragma unroll
            for (int mm = 0; mm < 32; mm += 4) {
                float4 dv  = *(float4*)&sm[OFF_DOCKT + fl * DKTLD + mb + mm];
                float4 av0 = *(float4*)&sm[OFF_ATTN + w * 128 + mb + mm];
                float4 av1 = *(float4*)&sm[OFF_ATTN + w * 128 + 64 + mb + mm];
                cc0 += av0.x * dv.x + av0.y * dv.y + av0.z * dv.z + av0.w * dv.w;
                cc1 += av1.x * dv.x + av1.y * dv.y + av1.z * dv.z + av1.w * dv.w;
            }
            cc0 += __shfl_xor_sync(~0u, cc0, 16);
            cc1 += __shfl_xor_sync(~0u, cc1, 16);
            if (lane < 16) {
                sm[OFF_CT + fl * CTLD + r0] = cc0;
                sm[OFF_CT + fl * CTLD + r1] = cc1;
            }
            __syncwarp();
        }
    }
    __syncthreads();

    // ---- 4. h_drone (FFMA2, Wdk from gmem) ----
    u64 hacc2[8] = {};
    #pragma unroll 4
    for (int hf = 0; hf < 64; hf++) {
        ulonglong2 wv = *(const ulonglong2*)&Wdk[hf * 128 + k4];
        float4 cv = *(float4*)&sm[OFF_CT + (hf & 15) * CTLD + (hf >> 4) * 32 + w * 4];
        u64 c0 = pk2(cv.x, cv.x), c1 = pk2(cv.y, cv.y);
        u64 c2 = pk2(cv.z, cv.z), c3 = pk2(cv.w, cv.w);
        fma2(hacc2[0], c0, wv.x); fma2(hacc2[1], c0, wv.y);
        fma2(hacc2[2], c1, wv.x); fma2(hacc2[3], c1, wv.y);
        fma2(hacc2[4], c2, wv.x); fma2(hacc2[5], c2, wv.y);
        fma2(hacc2[6], c3, wv.x); fma2(hacc2[7], c3, wv.y);
    }
    {
        float4 ho[4];
        #pragma unroll
        for (int i = 0; i < 4; i++) {
            float2 lo = up2(hacc2[2 * i]), hi = up2(hacc2[2 * i + 1]);
            ho[i].x = eluf(lo.x * 0.25f); ho[i].y = eluf(lo.y * 0.25f);
            ho[i].z = eluf(hi.x * 0.25f); ho[i].w = eluf(hi.y * 0.25f);
            *(float4*)&g_hd[((size_t)b * ND + w * 4 + i) * 128 + k4] = ho[i];
        }
        float4 u4 = *(float4*)&sm[OFF_U + k4];
        float pt[4];
        #pragma unroll
        for (int i = 0; i < 4; i++)
            pt[i] = ho[i].x * u4.x + ho[i].y * u4.y + ho[i].z * u4.z + ho[i].w * u4.w;
        #pragma unroll
        for (int i = 0; i < 4; i++)
            #pragma unroll
            for (int o = 16; o; o >>= 1) pt[i] += __shfl_xor_sync(~0u, pt[i], o);
        if (lane == 0) {
            float s0v = g_s0[0];
            #pragma unroll
            for (int i = 0; i < 4; i++) sm[OFF_T + w * 4 + i] = pt[i] + s0v;
        }
        *(float4*)&sm[OFF_HDT + (k4 + 0) * HDTLD + w * 4] = make_float4(ho[0].x, ho[1].x, ho[2].x, ho[3].x);
        *(float4*)&sm[OFF_HDT + (k4 + 1) * HDTLD + w * 4] = make_float4(ho[0].y, ho[1].y, ho[2].y, ho[3].y);
        *(float4*)&sm[OFF_HDT + (k4 + 2) * HDTLD + w * 4] = make_float4(ho[0].z, ho[1].z, ho[2].z, ho[3].z);
        *(float4*)&sm[OFF_HDT + (k4 + 3) * HDTLD + w * 4] = make_float4(ho[0].w, ho[1].w, ho[2].w, ho[3].w);
    }
    __syncthreads();

    // ---- 5. r = hd @ M + vb (FFMA2, M from gmem/L2) ----
    {
        const int n0 = (t & 15) * 2, j0 = (t >> 4) * 8;
        u64 acc2[2][4] = {};
        #pragma unroll 8
        for (int al = 0; al < 128; al++) {
            ulonglong2 m01 = *(const ulonglong2*)&g_M[al * 128 + j0];
            ulonglong2 m23 = *(const ulonglong2*)&g_M[al * 128 + j0 + 4];
            float2 hv = *(float2*)&sm[OFF_HDT + al * HDTLD + n0];
            u64 h0 = pk2(hv.x, hv.x), h1 = pk2(hv.y, hv.y);
            fma2(acc2[0][0], h0, m01.x); fma2(acc2[0][1], h0, m01.y);
            fma2(acc2[0][2], h0, m23.x); fma2(acc2[0][3], h0, m23.y);
            fma2(acc2[1][0], h1, m01.x); fma2(acc2[1][1], h1, m01.y);
            fma2(acc2[1][2], h1, m23.x); fma2(acc2[1][3], h1, m23.y);
        }
        __syncthreads();
        #pragma unroll
        for (int jp = 0; jp < 4; jp++) {
            float2 a0 = up2(acc2[0][jp]);
            float2 a1 = up2(acc2[1][jp]);
            float vb0 = sm[OFF_VB + j0 + 2 * jp], vb1 = sm[OFF_VB + j0 + 2 * jp + 1];
            *(float2*)&sm[OFF_RT + (j0 + 2 * jp) * RTLD + n0]     = make_float2(a0.x + vb0, a1.x + vb0);
            *(float2*)&sm[OFF_RT + (j0 + 2 * jp + 1) * RTLD + n0] = make_float2(a0.y + vb1, a1.y + vb1);
        }
    }
    __syncthreads();

    // ---- 6. h_dock (FFMA2, wbar from gmem) ----
    {
        const int m0 = (t & 7) * 8, k0 = (t >> 3) * 4;
        u64 acc2[8][2] = {};
        #pragma unroll
        for (int f = 0; f < 16; f++) {
            ulonglong2 wv = *(const ulonglong2*)&g_wbar[f * 128 + k0];
            float4 da = *(float4*)&sm[OFF_DOCKT + f * DKTLD + m0];
            float4 db = *(float4*)&sm[OFF_DOCKT + f * DKTLD + m0 + 4];
            u64 d0 = pk2(da.x, da.x), d1 = pk2(da.y, da.y), d2 = pk2(da.z, da.z), d3 = pk2(da.w, da.w);
            u64 d4 = pk2(db.x, db.x), d5 = pk2(db.y, db.y), d6 = pk2(db.z, db.z), d7 = pk2(db.w, db.w);
            fma2(acc2[0][0], d0, wv.x); fma2(acc2[0][1], d0, wv.y);
            fma2(acc2[1][0], d1, wv.x); fma2(acc2[1][1], d1, wv.y);
            fma2(acc2[2][0], d2, wv.x); fma2(acc2[2][1], d2, wv.y);
            fma2(acc2[3][0], d3, wv.x); fma2(acc2[3][1], d3, wv.y);
            fma2(acc2[4][0], d4, wv.x); fma2(acc2[4][1], d4, wv.y);
            fma2(acc2[5][0], d5, wv.x); fma2(acc2[5][1], d5, wv.y);
            fma2(acc2[6][0], d6, wv.x); fma2(acc2[6][1], d6, wv.y);
            fma2(acc2[7][0], d7, wv.x); fma2(acc2[7][1], d7, wv.y);
        }
        float accf[8][4];
        #pragma unroll
        for (int m = 0; m < 8; m++) {
            float2 a = up2(acc2[m][0]), bq = up2(acc2[m][1]);
            accf[m][0] = a.x; accf[m][1] = a.y; accf[m][2] = bq.x; accf[m][3] = bq.y;
        }
        #pragma unroll
        for (int q = 0; q < 4; q++) {
            float4 va = make_float4(eluf(accf[0][q]), eluf(accf[1][q]), eluf(accf[2][q]), eluf(accf[3][q]));
            float4 vb4 = make_float4(eluf(accf[4][q]), eluf(accf[5][q]), eluf(accf[6][q]), eluf(accf[7][q]));
            *(float4*)&sm[OFF_HKT + (k0 + q) * HKTLD + m0] = va;
            *(float4*)&sm[OFF_HKT + (k0 + q) * HKTLD + m0 + 4] = vb4;
        }
    }
    __syncthreads();

    // ---- 7. logits (FFMA2): tile 2n x 4m, adj from gmem ----
    {
        const int n0 = (t >> 4) * 2, m0 = (t & 15) * 4;
        const float* adjp = rowp + 1536;
        float4 j0v = *(const float4*)&adjp[n0 * 64 + m0];
        float4 j1v = *(const float4*)&adjp[(n0 + 1) * 64 + m0];
        u64 acc2[2][2] = {};
        #pragma unroll 4
        for (int j = 0; j < 128; j++) {
            float2 rv = *(float2*)&sm[OFF_RT + j * RTLD + n0];
            ulonglong2 hv = *(ulonglong2*)&sm[OFF_HKT + j * HKTLD + m0];
            u64 r0 = pk2(rv.x, rv.x), r1 = pk2(rv.y, rv.y);
            fma2(acc2[0][0], r0, hv.x); fma2(acc2[0][1], r0, hv.y);
            fma2(acc2[1][0], r1, hv.x); fma2(acc2[1][1], r1, hv.y);
        }
        float2 p00 = up2(acc2[0][0]), p01 = up2(acc2[0][1]);
        float2 p10 = up2(acc2[1][0]), p11 = up2(acc2[1][1]);
        float t0 = sm[OFF_T + n0], t1 = sm[OFF_T + n0 + 1];
        float4 o0, o1;
        o0.x = j0v.x > 0.f ? p00.x + t0 : NEGV; o0.y = j0v.y > 0.f ? p00.y + t0 : NEGV;
        o0.z = j0v.z > 0.f ? p01.x + t0 : NEGV; o0.w = j0v.w > 0.f ? p01.y + t0 : NEGV;
        o1.x = j1v.x > 0.f ? p10.x + t1 : NEGV; o1.y = j1v.y > 0.f ? p10.y + t1 : NEGV;
        o1.z = j1v.z > 0.f ? p11.x + t1 : NEGV; o1.w = j1v.w > 0.f ? p11.y + t1 : NEGV;
        float* op = out_logits + (size_t)b * 2048;
        *(float4*)&op[n0 * 64 + m0] = o0;
        *(float4*)&op[(n0 + 1) * 64 + m0] = o1;
    }
}

// ================= critic: split-K(8) FFMA2 GEMM then combine =================
__global__ void __launch_bounds__(256) critic_gemm(const float* __restrict__ Wc1)
{
    __shared__ float s_chunk[32 * 128];
    const int t = threadIdx.x;
    const int b0 = blockIdx.x * 32;
    const int kb = blockIdx.y * 512;
    const int jp = (t & 15) * 4;          // 4 j per thread (u64 x2, contiguous in Wc1)
    const int rr = (t >> 4) * 2;          // 2 rows per thread
    u64 acc2[2][2] = {};

    for (int c = 0; c < 4; c++) {
        const int kbase = kb + c * 128;
        __syncthreads();
        for (int idx = t; idx < 1024; idx += 256) {
            int r = idx >> 5, c4 = (idx & 31) * 4;
            *(float4*)&s_chunk[r * 128 + c4] =
                *(const float4*)&g_hd[(size_t)(b0 + r) * 4096 + kbase + c4];
        }
        __syncthreads();
        const float* wbase = Wc1 + (size_t)kbase * 64 + jp;
        #pragma unroll 4
        for (int k = 0; k < 128; k++) {
            ulonglong2 wv = *(const ulonglong2*)(wbase + (size_t)k * 64);
            float h0 = s_chunk[rr * 128 + k];
            float h1 = s_chunk[(rr + 1) * 128 + k];
            u64 hh0 = pk2(h0, h0), hh1 = pk2(h1, h1);
            fma2(acc2[0][0], hh0, wv.x); fma2(acc2[0][1], hh0, wv.y);
            fma2(acc2[1][0], hh1, wv.x); fma2(acc2[1][1], hh1, wv.y);
        }
    }
    #pragma unroll
    for (int r = 0; r < 2; r++) {
        float2 a = up2(acc2[r][0]), b2 = up2(acc2[r][1]);
        float4 v = make_float4(a.x, a.y, b2.x, b2.y);
        *(float4*)&g_hpart[((size_t)blockIdx.y * NB + b0 + rr + r) * 64 + jp] = v;
    }
}

__global__ void __launch_bounds__(256) critic_final(
    const float* __restrict__ bc1, const float* __restrict__ Wc2,
    const float* __restrict__ bc2, float* __restrict__ out_values)
{
    const int w = threadIdx.x >> 5, lane = threadIdx.x & 31;
    const int b = blockIdx.x * 8 + w;
    float a = 0.f;
    #pragma unroll
    for (int half = 0; half < 2; half++) {
        int jj = lane + 32 * half;
        size_t o = (size_t)b * 64 + jj;
        float h = bc1[jj];
        #pragma unroll
        for (int p = 0; p < 8; p++) h += g_hpart[(size_t)p * NB * 64 + o];
        a += (h > 0.f ? h : 0.f) * Wc2[jj];
    }
    #pragma unroll
    for (int o = 16; o; o >>= 1) a += __shfl_xor_sync(~0u, a, o);
    if (lane == 0) out_values[b] = a + bc2[0];
}

extern "C" void kernel_launch(void* const* d_in, const int* in_sizes, int n_in,
                              void* d_out, int out_size)
{
    const float* obs  = (const float*)d_in[0];
    const float* Wdr  = (const float*)d_in[1];
    const float* Wdk  = (const float*)d_in[2];
    const float* asrc = (const float*)d_in[3];
    const float* adst = (const float*)d_in[4];
    const float* Wc1  = (const float*)d_in[5];
    const float* bc1  = (const float*)d_in[6];
    const float* Wc2  = (const float*)d_in[7];
    const float* bc2  = (const float*)d_in[8];
    const float* Wad  = (const float*)d_in[9];
    const float* bad  = (const float*)d_in[10];
    const float* Wak  = (const float*)d_in[11];
    const float* bak  = (const float*)d_in[12];

    float* out        = (float*)d_out;
    float* out_values = out;
    float* out_logits = out + NB;

    cudaFuncSetAttribute(gat_main, cudaFuncAttributeMaxDynamicSharedMemorySize,
                         SMF * (int)sizeof(float));

    precomp<<<17, 256>>>(Wdr, Wdk, asrc, adst, Wad, Wak, bad, bak);
    gat_main<<<NB, 256, SMF * sizeof(float)>>>(obs, Wdk, out_logits);
    critic_gemm<<<dim3(NB / 32, 8), 256>>>(Wc1);
    critic_final<<<NB / 8, 256>>>(bc1, Wc2, bc2, out_values);
}

// round 14
// speedup vs baseline: 1.1936x; 1.0894x over previous
#include <cuda_runtime.h>

#define NB 4096
#define ND 32
#define NK 64
#define NHID 128
#define ALPHA 0.2f
#define NEGV (-9e15f)
#define OBSW 3584

// ---- gat_main smem layout (float offsets) ---- (R8-identical)
#define OFF_ADJ   0        // 2048  dead after attn
#define OFF_CT    2048     // 2112  dead after h_drone
#define CTLD 132
#define OFF_RT    0        // 4096  written in r-GEMM (over ADJ+CT)
#define RTLD 32
#define OFF_DOCKT 4160     // 1088  live until h_dock
#define DKTLD 68
#define OFF_HDT   5248     // 4608  dead after r-GEMM
#define HDTLD 36
#define OFF_HKT   5248     // 8192  written in h_dock (over HDT)
#define HKTLD 64
#define OFF_SRC   9856     // 128
#define OFF_DST   9984     // 256
#define OFF_VS    10240    // 64
#define OFF_VD    10304    // 64
#define OFF_ATTN  10368    // 1024 (128 per warp: 2 rows)
#define OFF_DRONE 11392    // 512
#define OFF_U     13440    // 128
#define OFF_VB    13568    // 128
#define OFF_T     13696    // 32
#define SMF       13728    // 54912 B -> 4 CTAs/SM

#define KSPLIT 16

typedef unsigned long long u64;
typedef unsigned int u32;

__device__ __forceinline__ u64 pk2(float lo, float hi) {
    u64 r; asm("mov.b64 %0,{%1,%2};" : "=l"(r) : "f"(lo), "f"(hi)); return r;
}
__device__ __forceinline__ void fma2(u64& d, u64 a, u64 b) {
    asm("fma.rn.f32x2 %0, %1, %2, %0;" : "+l"(d) : "l"(a), "l"(b));
}
__device__ __forceinline__ float2 up2(u64 v) {
    float2 f; asm("mov.b64 {%0,%1},%2;" : "=f"(f.x), "=f"(f.y) : "l"(v)); return f;
}

__device__ float g_hd[(size_t)NB * ND * NHID];      // 64 MB
__device__ float g_hpart[(size_t)KSPLIT * NB * 64]; // 16 MB critic partials
__device__ float g_M[NHID * NHID];
__device__ float g_vb[NHID];
__device__ float g_u[NHID];
__device__ float g_s0[1];
__device__ float g_vsrc[64];
__device__ float g_vdst[64];
__device__ float g_wbar[16 * NHID];

__device__ __forceinline__ float eluf(float x) { return x > 0.f ? x : expm1f(x); }

// ================= precompute (batch-independent), grid=17 =================
__global__ void precomp(const float* __restrict__ Wdr, const float* __restrict__ Wdk,
                        const float* __restrict__ asrc, const float* __restrict__ adst,
                        const float* __restrict__ Wad, const float* __restrict__ Wak,
                        const float* __restrict__ bad, const float* __restrict__ bak)
{
    const int t = threadIdx.x;
    if (blockIdx.x < 16) {
        __shared__ float swad[8 * 128];
        __shared__ float swak[32 * 128];
        const int a0 = blockIdx.x * 8;
        for (int i = t; i < 1024; i += 256) swad[i] = Wad[a0 * 128 + i];
        for (int jb = 0; jb < 4; jb++) {
            __syncthreads();
            for (int i = t; i < 4096; i += 256) swak[i] = Wak[jb * 4096 + i];
            __syncthreads();
            const int aa = t >> 5, jl = t & 31;
            float s = 0.f;
            for (int c = 0; c < 128; c++) {
                int cc = (c + jl) & 127;
                s += swad[aa * 128 + cc] * swak[jl * 128 + cc];
            }
            g_M[(a0 + aa) * 128 + jb * 32 + jl] = s;
        }
        if (t < 8) {
            float s = 0.f;
            for (int c = 0; c < 128; c++) s += swad[t * 128 + c] * bak[c];
            g_u[a0 + t] = s;
        }
    } else {
        __shared__ float sb[128];
        if (t < 128) sb[t] = bad[t];
        __syncthreads();
        if (t < 128) {
            float s = 0.f;
            for (int c = 0; c < 128; c++) s += sb[c] * Wak[t * 128 + c];
            g_vb[t] = s;
        }
        if (t == 0) {
            float s = 0.f;
            for (int c = 0; c < 128; c++) s += sb[c] * bak[c];
            g_s0[0] = s;
        }
        if (t < 64) {
            int h = t >> 4, f = t & 15;
            float s = 0.f;
            for (int c = 0; c < 128; c++) s += Wdr[(h * 16 + f) * 128 + c] * asrc[h * 128 + c];
            g_vsrc[t] = s;
        } else if (t < 128) {
            int u2 = t - 64, h = u2 >> 4, f = u2 & 15;
            float s = 0.f;
            for (int c = 0; c < 128; c++) s += Wdk[(h * 16 + f) * 128 + c] * adst[h * 128 + c];
            g_vdst[u2] = s;
        }
        for (int i = t; i < 2048; i += 256) {
            float s = Wdk[i] + Wdk[2048 + i] + Wdk[4096 + i] + Wdk[6144 + i];
            g_wbar[i] = s * 0.25f;
        }
    }
}

// ================= per-batch kernel (R8-identical) =================
__global__ void __launch_bounds__(256, 4) gat_main(
    const float* __restrict__ obs, const float* __restrict__ Wdk,
    float* __restrict__ out_logits)
{
    extern __shared__ float sm[];
    const int b = blockIdx.x, t = threadIdx.x;
    const int w = t >> 5, lane = t & 31;
    const int k4 = lane * 4;
    const float* rowp = obs + (size_t)b * OBSW;

    // ---- 1. load per-batch data ----
    for (int i = t; i < 512;  i += 256) sm[OFF_DRONE + i] = rowp[i];
    for (int i = t; i < 1024; i += 256) {
        int m = i >> 4, f = i & 15;
        sm[OFF_DOCKT + f * DKTLD + m] = rowp[512 + i];
    }
    for (int i = t; i < 2048; i += 256) sm[OFF_ADJ + i] = rowp[1536 + i];
    if (t < 64)       sm[OFF_VS + t]       = g_vsrc[t];
    else if (t < 128) sm[OFF_VD + t - 64]  = g_vdst[t - 64];
    else              sm[OFF_VB + t - 128] = g_vb[t - 128];
    for (int i = t; i < 128; i += 256) sm[OFF_U + i] = g_u[i];
    __syncthreads();

    // ---- 2. src[h,n], dst[h,m] ----
    if (t < 128) {
        int h = t >> 5, n = t & 31;
        float s = 0.f;
        #pragma unroll
        for (int f = 0; f < 16; f++) s += sm[OFF_DRONE + n * 16 + f] * sm[OFF_VS + h * 16 + f];
        sm[OFF_SRC + t] = s;
    }
    {
        int h = t >> 6, m = t & 63;
        float s = 0.f;
        #pragma unroll
        for (int f = 0; f < 16; f++) s += sm[OFF_DOCKT + f * DKTLD + m] * sm[OFF_VD + h * 16 + f];
        sm[OFF_DST + h * 64 + m] = s;
    }
    __syncthreads();

    // ---- 3. attention: paired rows, softmax + cT[f][r] ----
    {
        const int h = w >> 1;
        const int fl = lane & 15, mb = (lane >> 4) * 32;
        const float d0 = sm[OFF_DST + h * 64 + lane];
        const float d1 = sm[OFF_DST + h * 64 + 32 + lane];
        for (int rp = 0; rp < 8; rp++) {
            const int r0 = w * 16 + rp * 2, r1 = r0 + 1;
            const int n0 = r0 & 31, n1 = r1 & 31;
            float sc0 = sm[OFF_SRC + h * 32 + n0];
            float sc1 = sm[OFF_SRC + h * 32 + n1];
            float e00 = sc0 + d0, e01 = sc0 + d1, e10 = sc1 + d0, e11 = sc1 + d1;
            e00 = e00 > 0.f ? e00 : ALPHA * e00;
            e01 = e01 > 0.f ? e01 : ALPHA * e01;
            e10 = e10 > 0.f ? e10 : ALPHA * e10;
            e11 = e11 > 0.f ? e11 : ALPHA * e11;
            if (!(sm[OFF_ADJ + n0 * 64 + lane] > 0.f))      e00 = NEGV;
            if (!(sm[OFF_ADJ + n0 * 64 + 32 + lane] > 0.f)) e01 = NEGV;
            if (!(sm[OFF_ADJ + n1 * 64 + lane] > 0.f))      e10 = NEGV;
            if (!(sm[OFF_ADJ + n1 * 64 + 32 + lane] > 0.f)) e11 = NEGV;
            float mx0 = fmaxf(e00, e01), mx1 = fmaxf(e10, e11);
            #pragma unroll
            for (int o = 16; o; o >>= 1) {
                mx0 = fmaxf(mx0, __shfl_xor_sync(~0u, mx0, o));
                mx1 = fmaxf(mx1, __shfl_xor_sync(~0u, mx1, o));
            }
            float p00 = __expf(e00 - mx0), p01 = __expf(e01 - mx0);
            float p10 = __expf(e10 - mx1), p11 = __expf(e11 - mx1);
            float su0 = p00 + p01, su1 = p10 + p11;
            #pragma unroll
            for (int o = 16; o; o >>= 1) {
                su0 += __shfl_xor_sync(~0u, su0, o);
                su1 += __shfl_xor_sync(~0u, su1, o);
            }
            float iv0 = 1.0f / su0, iv1 = 1.0f / su1;
            sm[OFF_ATTN + w * 128 + lane]       = p00 * iv0;
            sm[OFF_ATTN + w * 128 + 32 + lane]  = p01 * iv0;
            sm[OFF_ATTN + w * 128 + 64 + lane]  = p10 * iv1;
            sm[OFF_ATTN + w * 128 + 96 + lane]  = p11 * iv1;
            __syncwarp();
            float cc0 = 0.f, cc1 = 0.f;
            #pragma unroll
            for (int mm = 0; mm < 32; mm += 4) {
                float4 dv  = *(float4*)&sm[OFF_DOCKT + fl * DKTLD + mb + mm];
                float4 av0 = *(float4*)&sm[OFF_ATTN + w * 128 + mb + mm];
                float4 av1 = *(float4*)&sm[OFF_ATTN + w * 128 + 64 + mb + mm];
                cc0 += av0.x * dv.x + av0.y * dv.y + av0.z * dv.z + av0.w * dv.w;
                cc1 += av1.x * dv.x + av1.y * dv.y + av1.z * dv.z + av1.w * dv.w;
            }
            cc0 += __shfl_xor_sync(~0u, cc0, 16);
            cc1 += __shfl_xor_sync(~0u, cc1, 16);
            if (lane < 16) {
                sm[OFF_CT + fl * CTLD + r0] = cc0;
                sm[OFF_CT + fl * CTLD + r1] = cc1;
            }
            __syncwarp();
        }
    }
    __syncthreads();

    // ---- 4. h_drone (FFMA2, Wdk from gmem): warp w owns n=w*4..+3, lane owns k4 ----
    u64 hacc2[8] = {};
    #pragma unroll 4
    for (int hf = 0; hf < 64; hf++) {
        ulonglong2 wv = *(const ulonglong2*)&Wdk[hf * 128 + k4];
        float4 cv = *(float4*)&sm[OFF_CT + (hf & 15) * CTLD + (hf >> 4) * 32 + w * 4];
        u64 c0 = pk2(cv.x, cv.x), c1 = pk2(cv.y, cv.y);
        u64 c2 = pk2(cv.z, cv.z), c3 = pk2(cv.w, cv.w);
        fma2(hacc2[0], c0, wv.x); fma2(hacc2[1], c0, wv.y);
        fma2(hacc2[2], c1, wv.x); fma2(hacc2[3], c1, wv.y);
        fma2(hacc2[4], c2, wv.x); fma2(hacc2[5], c2, wv.y);
        fma2(hacc2[6], c3, wv.x); fma2(hacc2[7], c3, wv.y);
    }
    {
        float4 ho[4];
        #pragma unroll
        for (int i = 0; i < 4; i++) {
            float2 lo = up2(hacc2[2 * i]), hi = up2(hacc2[2 * i + 1]);
            ho[i].x = eluf(lo.x * 0.25f); ho[i].y = eluf(lo.y * 0.25f);
            ho[i].z = eluf(hi.x * 0.25f); ho[i].w = eluf(hi.y * 0.25f);
            *(float4*)&g_hd[((size_t)b * ND + w * 4 + i) * 128 + k4] = ho[i];
        }
        // t[n] = hd[n,:].u + s0 via warp reduce
        float4 u4 = *(float4*)&sm[OFF_U + k4];
        float pt[4];
        #pragma unroll
        for (int i = 0; i < 4; i++)
            pt[i] = ho[i].x * u4.x + ho[i].y * u4.y + ho[i].z * u4.z + ho[i].w * u4.w;
        #pragma unroll
        for (int i = 0; i < 4; i++)
            #pragma unroll
            for (int o = 16; o; o >>= 1) pt[i] += __shfl_xor_sync(~0u, pt[i], o);
        if (lane == 0) {
            float s0v = g_s0[0];
            #pragma unroll
            for (int i = 0; i < 4; i++) sm[OFF_T + w * 4 + i] = pt[i] + s0v;
        }
        *(float4*)&sm[OFF_HDT + (k4 + 0) * HDTLD + w * 4] = make_float4(ho[0].x, ho[1].x, ho[2].x, ho[3].x);
        *(float4*)&sm[OFF_HDT + (k4 + 1) * HDTLD + w * 4] = make_float4(ho[0].y, ho[1].y, ho[2].y, ho[3].y);
        *(float4*)&sm[OFF_HDT + (k4 + 2) * HDTLD + w * 4] = make_float4(ho[0].z, ho[1].z, ho[2].z, ho[3].z);
        *(float4*)&sm[OFF_HDT + (k4 + 3) * HDTLD + w * 4] = make_float4(ho[0].w, ho[1].w, ho[2].w, ho[3].w);
    }
    __syncthreads();

    // ---- 5. r = hd @ M + vb (FFMA2, M from gmem/L2): tile 2n x 8j -> rT[j][n] ----
    {
        const int n0 = (t & 15) * 2, j0 = (t >> 4) * 8;
        u64 acc2[2][4] = {};
        #pragma unroll 8
        for (int al = 0; al < 128; al++) {
            ulonglong2 m01 = *(const ulonglong2*)&g_M[al * 128 + j0];
            ulonglong2 m23 = *(const ulonglong2*)&g_M[al * 128 + j0 + 4];
            float2 hv = *(float2*)&sm[OFF_HDT + al * HDTLD + n0];
            u64 h0 = pk2(hv.x, hv.x), h1 = pk2(hv.y, hv.y);
            fma2(acc2[0][0], h0, m01.x); fma2(acc2[0][1], h0, m01.y);
            fma2(acc2[0][2], h0, m23.x); fma2(acc2[0][3], h0, m23.y);
            fma2(acc2[1][0], h1, m01.x); fma2(acc2[1][1], h1, m01.y);
            fma2(acc2[1][2], h1, m23.x); fma2(acc2[1][3], h1, m23.y);
        }
        __syncthreads();   // HDT reads done everywhere; RT region (over ADJ/CT) now writable
        #pragma unroll
        for (int jp = 0; jp < 4; jp++) {
            float2 a0 = up2(acc2[0][jp]);
            float2 a1 = up2(acc2[1][jp]);
            float vb0 = sm[OFF_VB + j0 + 2 * jp], vb1 = sm[OFF_VB + j0 + 2 * jp + 1];
            *(float2*)&sm[OFF_RT + (j0 + 2 * jp) * RTLD + n0]     = make_float2(a0.x + vb0, a1.x + vb0);
            *(float2*)&sm[OFF_RT + (j0 + 2 * jp + 1) * RTLD + n0] = make_float2(a0.y + vb1, a1.y + vb1);
        }
    }
    __syncthreads();

    // ---- 6. h_dock (FFMA2, wbar from gmem): tile 8m x 4k -> hkT[k][m] (over HDT) ----
    {
        const int m0 = (t & 7) * 8, k0 = (t >> 3) * 4;
        u64 acc2[8][2] = {};
        #pragma unroll
        for (int f = 0; f < 16; f++) {
            ulonglong2 wv = *(const ulonglong2*)&g_wbar[f * 128 + k0];
            float4 da = *(float4*)&sm[OFF_DOCKT + f * DKTLD + m0];
            float4 db = *(float4*)&sm[OFF_DOCKT + f * DKTLD + m0 + 4];
            u64 d0 = pk2(da.x, da.x), d1 = pk2(da.y, da.y), d2 = pk2(da.z, da.z), d3 = pk2(da.w, da.w);
            u64 d4 = pk2(db.x, db.x), d5 = pk2(db.y, db.y), d6 = pk2(db.z, db.z), d7 = pk2(db.w, db.w);
            fma2(acc2[0][0], d0, wv.x); fma2(acc2[0][1], d0, wv.y);
            fma2(acc2[1][0], d1, wv.x); fma2(acc2[1][1], d1, wv.y);
            fma2(acc2[2][0], d2, wv.x); fma2(acc2[2][1], d2, wv.y);
            fma2(acc2[3][0], d3, wv.x); fma2(acc2[3][1], d3, wv.y);
            fma2(acc2[4][0], d4, wv.x); fma2(acc2[4][1], d4, wv.y);
            fma2(acc2[5][0], d5, wv.x); fma2(acc2[5][1], d5, wv.y);
            fma2(acc2[6][0], d6, wv.x); fma2(acc2[6][1], d6, wv.y);
            fma2(acc2[7][0], d7, wv.x); fma2(acc2[7][1], d7, wv.y);
        }
        float accf[8][4];
        #pragma unroll
        for (int m = 0; m < 8; m++) {
            float2 a = up2(acc2[m][0]), bq = up2(acc2[m][1]);
            accf[m][0] = a.x; accf[m][1] = a.y; accf[m][2] = bq.x; accf[m][3] = bq.y;
        }
        #pragma unroll
        for (int q = 0; q < 4; q++) {
            float4 va = make_float4(eluf(accf[0][q]), eluf(accf[1][q]), eluf(accf[2][q]), eluf(accf[3][q]));
            float4 vb4 = make_float4(eluf(accf[4][q]), eluf(accf[5][q]), eluf(accf[6][q]), eluf(accf[7][q]));
            *(float4*)&sm[OFF_HKT + (k0 + q) * HKTLD + m0] = va;
            *(float4*)&sm[OFF_HKT + (k0 + q) * HKTLD + m0 + 4] = vb4;
        }
    }
    __syncthreads();

    // ---- 7. logits (FFMA2): tile 2n x 4m, adj from gmem ----
    {
        const int n0 = (t >> 4) * 2, m0 = (t & 15) * 4;
        const float* adjp = rowp + 1536;
        float4 j0v = *(const float4*)&adjp[n0 * 64 + m0];
        float4 j1v = *(const float4*)&adjp[(n0 + 1) * 64 + m0];
        u64 acc2[2][2] = {};
        #pragma unroll 4
        for (int j = 0; j < 128; j++) {
            float2 rv = *(float2*)&sm[OFF_RT + j * RTLD + n0];
            ulonglong2 hv = *(ulonglong2*)&sm[OFF_HKT + j * HKTLD + m0];
            u64 r0 = pk2(rv.x, rv.x), r1 = pk2(rv.y, rv.y);
            fma2(acc2[0][0], r0, hv.x); fma2(acc2[0][1], r0, hv.y);
            fma2(acc2[1][0], r1, hv.x); fma2(acc2[1][1], r1, hv.y);
        }
        float2 p00 = up2(acc2[0][0]), p01 = up2(acc2[0][1]);
        float2 p10 = up2(acc2[1][0]), p11 = up2(acc2[1][1]);
        float t0 = sm[OFF_T + n0], t1 = sm[OFF_T + n0 + 1];
        float4 o0, o1;
        o0.x = j0v.x > 0.f ? p00.x + t0 : NEGV; o0.y = j0v.y > 0.f ? p00.y + t0 : NEGV;
        o0.z = j0v.z > 0.f ? p01.x + t0 : NEGV; o0.w = j0v.w > 0.f ? p01.y + t0 : NEGV;
        o1.x = j1v.x > 0.f ? p10.x + t1 : NEGV; o1.y = j1v.y > 0.f ? p10.y + t1 : NEGV;
        o1.z = j1v.z > 0.f ? p11.x + t1 : NEGV; o1.w = j1v.w > 0.f ? p11.y + t1 : NEGV;
        float* op = out_logits + (size_t)b * 2048;
        *(float4*)&op[n0 * 64 + m0] = o0;
        *(float4*)&op[(n0 + 1) * 64 + m0] = o1;
    }
}

// ================= critic: split-K(16) GEMM then combine =================
__global__ void __launch_bounds__(256) critic_gemm(const float* __restrict__ Wc1)
{
    __shared__ float s_chunk[32 * 128];
    const int t = threadIdx.x;
    const int b0 = blockIdx.x * 32;
    const int kb = blockIdx.y * 256;
    const int j = t & 63, rg = t >> 6;
    float acc[8] = {};

    for (int c = 0; c < 2; c++) {
        const int kbase = kb + c * 128;
        __syncthreads();
        for (int idx = t; idx < 1024; idx += 256) {
            int r = idx >> 5, c4 = (idx & 31) * 4;
            *(float4*)&s_chunk[r * 128 + c4] =
                *(const float4*)&g_hd[(size_t)(b0 + r) * 4096 + kbase + c4];
        }
        __syncthreads();
        for (int ii = 0; ii < 128; ii += 4) {
            float w0 = Wc1[(size_t)(kbase + ii    ) * 64 + j];
            float w1 = Wc1[(size_t)(kbase + ii + 1) * 64 + j];
            float w2 = Wc1[(size_t)(kbase + ii + 2) * 64 + j];
            float w3 = Wc1[(size_t)(kbase + ii + 3) * 64 + j];
            #pragma unroll
            for (int r = 0; r < 8; r++) {
                float4 h4 = *(const float4*)&s_chunk[(rg * 8 + r) * 128 + ii];
                acc[r] += h4.x * w0 + h4.y * w1 + h4.z * w2 + h4.w * w3;
            }
        }
    }
    #pragma unroll
    for (int r = 0; r < 8; r++)
        g_hpart[((size_t)blockIdx.y * NB + b0 + rg * 8 + r) * 64 + j] = acc[r];
}

__global__ void __launch_bounds__(256) critic_final(
    const float* __restrict__ bc1, const float* __restrict__ Wc2,
    const float* __restrict__ bc2, float* __restrict__ out_values)
{
    const int w = threadIdx.x >> 5, lane = threadIdx.x & 31;
    const int b = blockIdx.x * 8 + w;
    float a = 0.f;
    #pragma unroll
    for (int half = 0; half < 2; half++) {
        int jj = lane + 32 * half;
        size_t o = (size_t)b * 64 + jj;
        float h = bc1[jj];
        #pragma unroll
        for (int p = 0; p < KSPLIT; p++) h += g_hpart[(size_t)p * NB * 64 + o];
        a += (h > 0.f ? h : 0.f) * Wc2[jj];
    }
    #pragma unroll
    for (int o = 16; o; o >>= 1) a += __shfl_xor_sync(~0u, a, o);
    if (lane == 0) out_values[b] = a + bc2[0];
}

extern "C" void kernel_launch(void* const* d_in, const int* in_sizes, int n_in,
                              void* d_out, int out_size)
{
    const float* obs  = (const float*)d_in[0];
    const float* Wdr  = (const float*)d_in[1];
    const float* Wdk  = (const float*)d_in[2];
    const float* asrc = (const float*)d_in[3];
    const float* adst = (const float*)d_in[4];
    const float* Wc1  = (const float*)d_in[5];
    const float* bc1  = (const float*)d_in[6];
    const float* Wc2  = (const float*)d_in[7];
    const float* bc2  = (const float*)d_in[8];
    const float* Wad  = (const float*)d_in[9];
    const float* bad  = (const float*)d_in[10];
    const float* Wak  = (const float*)d_in[11];
    const float* bak  = (const float*)d_in[12];

    float* out        = (float*)d_out;
    float* out_values = out;
    float* out_logits = out + NB;

    cudaFuncSetAttribute(gat_main, cudaFuncAttributeMaxDynamicSharedMemorySize,
                         SMF * (int)sizeof(float));

    precomp<<<17, 256>>>(Wdr, Wdk, asrc, adst, Wad, Wak, bad, bak);
    gat_main<<<NB, 256, SMF * sizeof(float)>>>(obs, Wdk, out_logits);
    critic_gemm<<<dim3(NB / 32, KSPLIT), 256>>>(Wc1);
    critic_final<<<NB / 8, 256>>>(bc1, Wc2, bc2, out_values);
}

// round 15
// speedup vs baseline: 1.2217x; 1.0236x over previous
#include <cuda_runtime.h>

#define NB 4096
#define ND 32
#define NK 64
#define NHID 128
#define ALPHA 0.2f
#define NEGV (-9e15f)
#define OBSW 3584

// ---- gat_main smem layout (float offsets) ---- (R8-identical)
#define OFF_ADJ   0        // 2048  dead after attn
#define OFF_CT    2048     // 2112  dead after h_drone
#define CTLD 132
#define OFF_RT    0        // 4096  written in r-GEMM (over ADJ+CT)
#define RTLD 32
#define OFF_DOCKT 4160     // 1088  live until h_dock
#define DKTLD 68
#define OFF_HDT   5248     // 4608  dead after r-GEMM
#define HDTLD 36
#define OFF_HKT   5248     // 8192  written in h_dock (over HDT)
#define HKTLD 64
#define OFF_SRC   9856     // 128
#define OFF_DST   9984     // 256
#define OFF_VS    10240    // 64
#define OFF_VD    10304    // 64
#define OFF_ATTN  10368    // 1024 (128 per warp: 2 rows)
#define OFF_DRONE 11392    // 512
#define OFF_U     13440    // 128
#define OFF_VB    13568    // 128
#define OFF_T     13696    // 32
#define SMF       13728    // 54912 B -> 4 CTAs/SM

#define KSPLIT 32

typedef unsigned long long u64;
typedef unsigned int u32;

__device__ __forceinline__ u64 pk2(float lo, float hi) {
    u64 r; asm("mov.b64 %0,{%1,%2};" : "=l"(r) : "f"(lo), "f"(hi)); return r;
}
__device__ __forceinline__ void fma2(u64& d, u64 a, u64 b) {
    asm("fma.rn.f32x2 %0, %1, %2, %0;" : "+l"(d) : "l"(a), "l"(b));
}
__device__ __forceinline__ float2 up2(u64 v) {
    float2 f; asm("mov.b64 {%0,%1},%2;" : "=f"(f.x), "=f"(f.y) : "l"(v)); return f;
}

__device__ float g_hd[(size_t)NB * ND * NHID];      // 64 MB
__device__ float g_hpart[(size_t)KSPLIT * NB * 64]; // 32 MB critic partials
__device__ float g_M[NHID * NHID];
__device__ float g_vb[NHID];
__device__ float g_u[NHID];
__device__ float g_s0[1];
__device__ float g_vsrc[64];
__device__ float g_vdst[64];
__device__ float g_wbar[16 * NHID];

__device__ __forceinline__ float eluf(float x) { return x > 0.f ? x : expm1f(x); }

// ================= precompute (batch-independent), grid=17 =================
__global__ void precomp(const float* __restrict__ Wdr, const float* __restrict__ Wdk,
                        const float* __restrict__ asrc, const float* __restrict__ adst,
                        const float* __restrict__ Wad, const float* __restrict__ Wak,
                        const float* __restrict__ bad, const float* __restrict__ bak)
{
    const int t = threadIdx.x;
    if (blockIdx.x < 16) {
        __shared__ float swad[8 * 128];
        __shared__ float swak[32 * 128];
        const int a0 = blockIdx.x * 8;
        for (int i = t; i < 1024; i += 256) swad[i] = Wad[a0 * 128 + i];
        for (int jb = 0; jb < 4; jb++) {
            __syncthreads();
            for (int i = t; i < 4096; i += 256) swak[i] = Wak[jb * 4096 + i];
            __syncthreads();
            const int aa = t >> 5, jl = t & 31;
            float s = 0.f;
            for (int c = 0; c < 128; c++) {
                int cc = (c + jl) & 127;
                s += swad[aa * 128 + cc] * swak[jl * 128 + cc];
            }
            g_M[(a0 + aa) * 128 + jb * 32 + jl] = s;
        }
        if (t < 8) {
            float s = 0.f;
            for (int c = 0; c < 128; c++) s += swad[t * 128 + c] * bak[c];
            g_u[a0 + t] = s;
        }
    } else {
        __shared__ float sb[128];
        if (t < 128) sb[t] = bad[t];
        __syncthreads();
        if (t < 128) {
            float s = 0.f;
            for (int c = 0; c < 128; c++) s += sb[c] * Wak[t * 128 + c];
            g_vb[t] = s;
        }
        if (t == 0) {
            float s = 0.f;
            for (int c = 0; c < 128; c++) s += sb[c] * bak[c];
            g_s0[0] = s;
        }
        if (t < 64) {
            int h = t >> 4, f = t & 15;
            float s = 0.f;
            for (int c = 0; c < 128; c++) s += Wdr[(h * 16 + f) * 128 + c] * asrc[h * 128 + c];
            g_vsrc[t] = s;
        } else if (t < 128) {
            int u2 = t - 64, h = u2 >> 4, f = u2 & 15;
            float s = 0.f;
            for (int c = 0; c < 128; c++) s += Wdk[(h * 16 + f) * 128 + c] * adst[h * 128 + c];
            g_vdst[u2] = s;
        }
        for (int i = t; i < 2048; i += 256) {
            float s = Wdk[i] + Wdk[2048 + i] + Wdk[4096 + i] + Wdk[6144 + i];
            g_wbar[i] = s * 0.25f;
        }
    }
}

// ================= per-batch kernel =================
__global__ void __launch_bounds__(256, 4) gat_main(
    const float* __restrict__ obs, const float* __restrict__ Wdk,
    float* __restrict__ out_logits)
{
    extern __shared__ float sm[];
    const int b = blockIdx.x, t = threadIdx.x;
    const int w = t >> 5, lane = t & 31;
    const int k4 = lane * 4;
    const float* rowp = obs + (size_t)b * OBSW;

    // ---- 1. load per-batch data ----
    for (int i = t; i < 512;  i += 256) sm[OFF_DRONE + i] = rowp[i];
    for (int i = t; i < 1024; i += 256) {
        int m = i >> 4, f = i & 15;
        sm[OFF_DOCKT + f * DKTLD + m] = rowp[512 + i];
    }
    for (int i = t; i < 2048; i += 256) sm[OFF_ADJ + i] = rowp[1536 + i];
    if (t < 64)       sm[OFF_VS + t]       = g_vsrc[t];
    else if (t < 128) sm[OFF_VD + t - 64]  = g_vdst[t - 64];
    else              sm[OFF_VB + t - 128] = g_vb[t - 128];
    for (int i = t; i < 128; i += 256) sm[OFF_U + i] = g_u[i];
    __syncthreads();

    // ---- 2. src[h,n], dst[h,m] ----
    if (t < 128) {
        int h = t >> 5, n = t & 31;
        float s = 0.f;
        #pragma unroll
        for (int f = 0; f < 16; f++) s += sm[OFF_DRONE + n * 16 + f] * sm[OFF_VS + h * 16 + f];
        sm[OFF_SRC + t] = s;
    }
    {
        int h = t >> 6, m = t & 63;
        float s = 0.f;
        #pragma unroll
        for (int f = 0; f < 16; f++) s += sm[OFF_DOCKT + f * DKTLD + m] * sm[OFF_VD + h * 16 + f];
        sm[OFF_DST + h * 64 + m] = s;
    }
    __syncthreads();

    // ---- 3. attention: paired rows, softmax + cT[f][r] ----
    {
        const int h = w >> 1;
        const int fl = lane & 15, mb = (lane >> 4) * 32;
        const float d0 = sm[OFF_DST + h * 64 + lane];
        const float d1 = sm[OFF_DST + h * 64 + 32 + lane];
        for (int rp = 0; rp < 8; rp++) {
            const int r0 = w * 16 + rp * 2, r1 = r0 + 1;
            const int n0 = r0 & 31, n1 = r1 & 31;
            float sc0 = sm[OFF_SRC + h * 32 + n0];
            float sc1 = sm[OFF_SRC + h * 32 + n1];
            float e00 = sc0 + d0, e01 = sc0 + d1, e10 = sc1 + d0, e11 = sc1 + d1;
            e00 = e00 > 0.f ? e00 : ALPHA * e00;
            e01 = e01 > 0.f ? e01 : ALPHA * e01;
            e10 = e10 > 0.f ? e10 : ALPHA * e10;
            e11 = e11 > 0.f ? e11 : ALPHA * e11;
            if (!(sm[OFF_ADJ + n0 * 64 + lane] > 0.f))      e00 = NEGV;
            if (!(sm[OFF_ADJ + n0 * 64 + 32 + lane] > 0.f)) e01 = NEGV;
            if (!(sm[OFF_ADJ + n1 * 64 + lane] > 0.f))      e10 = NEGV;
            if (!(sm[OFF_ADJ + n1 * 64 + 32 + lane] > 0.f)) e11 = NEGV;
            float mx0 = fmaxf(e00, e01), mx1 = fmaxf(e10, e11);
            #pragma unroll
            for (int o = 16; o; o >>= 1) {
                mx0 = fmaxf(mx0, __shfl_xor_sync(~0u, mx0, o));
                mx1 = fmaxf(mx1, __shfl_xor_sync(~0u, mx1, o));
            }
            float p00 = __expf(e00 - mx0), p01 = __expf(e01 - mx0);
            float p10 = __expf(e10 - mx1), p11 = __expf(e11 - mx1);
            float su0 = p00 + p01, su1 = p10 + p11;
            #pragma unroll
            for (int o = 16; o; o >>= 1) {
                su0 += __shfl_xor_sync(~0u, su0, o);
                su1 += __shfl_xor_sync(~0u, su1, o);
            }
            float iv0 = 1.0f / su0, iv1 = 1.0f / su1;
            sm[OFF_ATTN + w * 128 + lane]       = p00 * iv0;
            sm[OFF_ATTN + w * 128 + 32 + lane]  = p01 * iv0;
            sm[OFF_ATTN + w * 128 + 64 + lane]  = p10 * iv1;
            sm[OFF_ATTN + w * 128 + 96 + lane]  = p11 * iv1;
            __syncwarp();
            float cc0 = 0.f, cc1 = 0.f;
            #pragma unroll
            for (int mm = 0; mm < 32; mm += 4) {
                float4 dv  = *(float4*)&sm[OFF_DOCKT + fl * DKTLD + mb + mm];
                float4 av0 = *(float4*)&sm[OFF_ATTN + w * 128 + mb + mm];
                float4 av1 = *(float4*)&sm[OFF_ATTN + w * 128 + 64 + mb + mm];
                cc0 += av0.x * dv.x + av0.y * dv.y + av0.z * dv.z + av0.w * dv.w;
                cc1 += av1.x * dv.x + av1.y * dv.y + av1.z * dv.z + av1.w * dv.w;
            }
            cc0 += __shfl_xor_sync(~0u, cc0, 16);
            cc1 += __shfl_xor_sync(~0u, cc1, 16);
            if (lane < 16) {
                sm[OFF_CT + fl * CTLD + r0] = cc0;
                sm[OFF_CT + fl * CTLD + r1] = cc1;
            }
            __syncwarp();
        }
    }
    __syncthreads();

    // ---- 4. h_drone (FFMA2, Wdk from gmem): warp w owns n=w*4..+3, lane owns k4 ----
    u64 hacc2[8] = {};
    #pragma unroll 4
    for (int hf = 0; hf < 64; hf++) {
        ulonglong2 wv = *(const ulonglong2*)&Wdk[hf * 128 + k4];
        float4 cv = *(float4*)&sm[OFF_CT + (hf & 15) * CTLD + (hf >> 4) * 32 + w * 4];
        u64 c0 = pk2(cv.x, cv.x), c1 = pk2(cv.y, cv.y);
        u64 c2 = pk2(cv.z, cv.z), c3 = pk2(cv.w, cv.w);
        fma2(hacc2[0], c0, wv.x); fma2(hacc2[1], c0, wv.y);
        fma2(hacc2[2], c1, wv.x); fma2(hacc2[3], c1, wv.y);
        fma2(hacc2[4], c2, wv.x); fma2(hacc2[5], c2, wv.y);
        fma2(hacc2[6], c3, wv.x); fma2(hacc2[7], c3, wv.y);
    }
    {
        float4 ho[4];
        #pragma unroll
        for (int i = 0; i < 4; i++) {
            float2 lo = up2(hacc2[2 * i]), hi = up2(hacc2[2 * i + 1]);
            ho[i].x = eluf(lo.x * 0.25f); ho[i].y = eluf(lo.y * 0.25f);
            ho[i].z = eluf(hi.x * 0.25f); ho[i].w = eluf(hi.y * 0.25f);
            *(float4*)&g_hd[((size_t)b * ND + w * 4 + i) * 128 + k4] = ho[i];
        }
        // t[n] = hd[n,:].u + s0 via warp reduce
        float4 u4 = *(float4*)&sm[OFF_U + k4];
        float pt[4];
        #pragma unroll
        for (int i = 0; i < 4; i++)
            pt[i] = ho[i].x * u4.x + ho[i].y * u4.y + ho[i].z * u4.z + ho[i].w * u4.w;
        #pragma unroll
        for (int i = 0; i < 4; i++)
            #pragma unroll
            for (int o = 16; o; o >>= 1) pt[i] += __shfl_xor_sync(~0u, pt[i], o);
        if (lane == 0) {
            float s0v = g_s0[0];
            #pragma unroll
            for (int i = 0; i < 4; i++) sm[OFF_T + w * 4 + i] = pt[i] + s0v;
        }
        *(float4*)&sm[OFF_HDT + (k4 + 0) * HDTLD + w * 4] = make_float4(ho[0].x, ho[1].x, ho[2].x, ho[3].x);
        *(float4*)&sm[OFF_HDT + (k4 + 1) * HDTLD + w * 4] = make_float4(ho[0].y, ho[1].y, ho[2].y, ho[3].y);
        *(float4*)&sm[OFF_HDT + (k4 + 2) * HDTLD + w * 4] = make_float4(ho[0].z, ho[1].z, ho[2].z, ho[3].z);
        *(float4*)&sm[OFF_HDT + (k4 + 3) * HDTLD + w * 4] = make_float4(ho[0].w, ho[1].w, ho[2].w, ho[3].w);
    }
    __syncthreads();

    // ---- 5. r = hd @ M + vb (FFMA2, M from gmem/L2): tile 2n x 8j -> rT[j][n] ----
    {
        const int n0 = (t & 15) * 2, j0 = (t >> 4) * 8;
        u64 acc2[2][4] = {};
        #pragma unroll 8
        for (int al = 0; al < 128; al++) {
            ulonglong2 m01 = *(const ulonglong2*)&g_M[al * 128 + j0];
            ulonglong2 m23 = *(const ulonglong2*)&g_M[al * 128 + j0 + 4];
            float2 hv = *(float2*)&sm[OFF_HDT + al * HDTLD + n0];
            u64 h0 = pk2(hv.x, hv.x), h1 = pk2(hv.y, hv.y);
            fma2(acc2[0][0], h0, m01.x); fma2(acc2[0][1], h0, m01.y);
            fma2(acc2[0][2], h0, m23.x); fma2(acc2[0][3], h0, m23.y);
            fma2(acc2[1][0], h1, m01.x); fma2(acc2[1][1], h1, m01.y);
            fma2(acc2[1][2], h1, m23.x); fma2(acc2[1][3], h1, m23.y);
        }
        __syncthreads();   // HDT reads done everywhere; RT (over ADJ/CT) + HKT (over HDT) now writable
        #pragma unroll
        for (int jp = 0; jp < 4; jp++) {
            float2 a0 = up2(acc2[0][jp]);
            float2 a1 = up2(acc2[1][jp]);
            float vb0 = sm[OFF_VB + j0 + 2 * jp], vb1 = sm[OFF_VB + j0 + 2 * jp + 1];
            *(float2*)&sm[OFF_RT + (j0 + 2 * jp) * RTLD + n0]     = make_float2(a0.x + vb0, a1.x + vb0);
            *(float2*)&sm[OFF_RT + (j0 + 2 * jp + 1) * RTLD + n0] = make_float2(a0.y + vb1, a1.y + vb1);
        }
    }
    // (no barrier: phase 6 writes HKT which only conflicts with HDT reads,
    //  already fenced by the mid-phase-5 __syncthreads; RT/HKT/DOCKT disjoint)

    // ---- 6. h_dock (FFMA2, wbar from gmem): tile 8m x 4k -> hkT[k][m] (over HDT) ----
    {
        const int m0 = (t & 7) * 8, k0 = (t >> 3) * 4;
        u64 acc2[8][2] = {};
        #pragma unroll
        for (int f = 0; f < 16; f++) {
            ulonglong2 wv = *(const ulonglong2*)&g_wbar[f * 128 + k0];
            float4 da = *(float4*)&sm[OFF_DOCKT + f * DKTLD + m0];
            float4 db = *(float4*)&sm[OFF_DOCKT + f * DKTLD + m0 + 4];
            u64 d0 = pk2(da.x, da.x), d1 = pk2(da.y, da.y), d2 = pk2(da.z, da.z), d3 = pk2(da.w, da.w);
            u64 d4 = pk2(db.x, db.x), d5 = pk2(db.y, db.y), d6 = pk2(db.z, db.z), d7 = pk2(db.w, db.w);
            fma2(acc2[0][0], d0, wv.x); fma2(acc2[0][1], d0, wv.y);
            fma2(acc2[1][0], d1, wv.x); fma2(acc2[1][1], d1, wv.y);
            fma2(acc2[2][0], d2, wv.x); fma2(acc2[2][1], d2, wv.y);
            fma2(acc2[3][0], d3, wv.x); fma2(acc2[3][1], d3, wv.y);
            fma2(acc2[4][0], d4, wv.x); fma2(acc2[4][1], d4, wv.y);
            fma2(acc2[5][0], d5, wv.x); fma2(acc2[5][1], d5, wv.y);
            fma2(acc2[6][0], d6, wv.x); fma2(acc2[6][1], d6, wv.y);
            fma2(acc2[7][0], d7, wv.x); fma2(acc2[7][1], d7, wv.y);
        }
        float accf[8][4];
        #pragma unroll
        for (int m = 0; m < 8; m++) {
            float2 a = up2(acc2[m][0]), bq = up2(acc2[m][1]);
            accf[m][0] = a.x; accf[m][1] = a.y; accf[m][2] = bq.x; accf[m][3] = bq.y;
        }
        #pragma unroll
        for (int q = 0; q < 4; q++) {
            float4 va = make_float4(eluf(accf[0][q]), eluf(accf[1][q]), eluf(accf[2][q]), eluf(accf[3][q]));
            float4 vb4 = make_float4(eluf(accf[4][q]), eluf(accf[5][q]), eluf(accf[6][q]), eluf(accf[7][q]));
            *(float4*)&sm[OFF_HKT + (k0 + q) * HKTLD + m0] = va;
            *(float4*)&sm[OFF_HKT + (k0 + q) * HKTLD + m0 + 4] = vb4;
        }
    }
    __syncthreads();

    // ---- 7. logits (FFMA2): tile 2n x 4m, adj from gmem ----
    {
        const int n0 = (t >> 4) * 2, m0 = (t & 15) * 4;
        const float* adjp = rowp + 1536;
        float4 j0v = *(const float4*)&adjp[n0 * 64 + m0];
        float4 j1v = *(const float4*)&adjp[(n0 + 1) * 64 + m0];
        u64 acc2[2][2] = {};
        #pragma unroll 4
        for (int j = 0; j < 128; j++) {
            float2 rv = *(float2*)&sm[OFF_RT + j * RTLD + n0];
            ulonglong2 hv = *(ulonglong2*)&sm[OFF_HKT + j * HKTLD + m0];
            u64 r0 = pk2(rv.x, rv.x), r1 = pk2(rv.y, rv.y);
            fma2(acc2[0][0], r0, hv.x); fma2(acc2[0][1], r0, hv.y);
            fma2(acc2[1][0], r1, hv.x); fma2(acc2[1][1], r1, hv.y);
        }
        float2 p00 = up2(acc2[0][0]), p01 = up2(acc2[0][1]);
        float2 p10 = up2(acc2[1][0]), p11 = up2(acc2[1][1]);
        float t0 = sm[OFF_T + n0], t1 = sm[OFF_T + n0 + 1];
        float4 o0, o1;
        o0.x = j0v.x > 0.f ? p00.x + t0 : NEGV; o0.y = j0v.y > 0.f ? p00.y + t0 : NEGV;
        o0.z = j0v.z > 0.f ? p01.x + t0 : NEGV; o0.w = j0v.w > 0.f ? p01.y + t0 : NEGV;
        o1.x = j1v.x > 0.f ? p10.x + t1 : NEGV; o1.y = j1v.y > 0.f ? p10.y + t1 : NEGV;
        o1.z = j1v.z > 0.f ? p11.x + t1 : NEGV; o1.w = j1v.w > 0.f ? p11.y + t1 : NEGV;
        float* op = out_logits + (size_t)b * 2048;
        *(float4*)&op[n0 * 64 + m0] = o0;
        *(float4*)&op[(n0 + 1) * 64 + m0] = o1;
    }
}

// ================= critic: split-K(32) GEMM then combine =================
__global__ void __launch_bounds__(256) critic_gemm(const float* __restrict__ Wc1)
{
    __shared__ float s_chunk[32 * 128];
    const int t = threadIdx.x;
    const int b0 = blockIdx.x * 32;
    const int kbase = blockIdx.y * 128;
    const int j = t & 63, rg = t >> 6;
    float acc[8] = {};

    for (int idx = t; idx < 1024; idx += 256) {
        int r = idx >> 5, c4 = (idx & 31) * 4;
        *(float4*)&s_chunk[r * 128 + c4] =
            *(const float4*)&g_hd[(size_t)(b0 + r) * 4096 + kbase + c4];
    }
    __syncthreads();
    for (int ii = 0; ii < 128; ii += 4) {
        float w0 = Wc1[(size_t)(kbase + ii    ) * 64 + j];
        float w1 = Wc1[(size_t)(kbase + ii + 1) * 64 + j];
        float w2 = Wc1[(size_t)(kbase + ii + 2) * 64 + j];
        float w3 = Wc1[(size_t)(kbase + ii + 3) * 64 + j];
        #pragma unroll
        for (int r = 0; r < 8; r++) {
            float4 h4 = *(const float4*)&s_chunk[(rg * 8 + r) * 128 + ii];
            acc[r] += h4.x * w0 + h4.y * w1 + h4.z * w2 + h4.w * w3;
        }
    }
    #pragma unroll
    for (int r = 0; r < 8; r++)
        g_hpart[((size_t)blockIdx.y * NB + b0 + rg * 8 + r) * 64 + j] = acc[r];
}

__global__ void __launch_bounds__(256) critic_final(
    const float* __restrict__ bc1, const float* __restrict__ Wc2,
    const float* __restrict__ bc2, float* __restrict__ out_values)
{
    const int w = threadIdx.x >> 5, lane = threadIdx.x & 31;
    const int b = blockIdx.x * 8 + w;
    float a = 0.f;
    #pragma unroll
    for (int half = 0; half < 2; half++) {
        int jj = lane + 32 * half;
        size_t o = (size_t)b * 64 + jj;
        float h = bc1[jj];
        #pragma unroll 8
        for (int p = 0; p < KSPLIT; p++) h += g_hpart[(size_t)p * NB * 64 + o];
        a += (h > 0.f ? h : 0.f) * Wc2[jj];
    }
    #pragma unroll
    for (int o = 16; o; o >>= 1) a += __shfl_xor_sync(~0u, a, o);
    if (lane == 0) out_values[b] = a + bc2[0];
}

extern "C" void kernel_launch(void* const* d_in, const int* in_sizes, int n_in,
                              void* d_out, int out_size)
{
    const float* obs  = (const float*)d_in[0];
    const float* Wdr  = (const float*)d_in[1];
    const float* Wdk  = (const float*)d_in[2];
    const float* asrc = (const float*)d_in[3];
    const float* adst = (const float*)d_in[4];
    const float* Wc1  = (const float*)d_in[5];
    const float* bc1  = (const float*)d_in[6];
    const float* Wc2  = (const float*)d_in[7];
    const float* bc2  = (const float*)d_in[8];
    const float* Wad  = (const float*)d_in[9];
    const float* bad  = (const float*)d_in[10];
    const float* Wak  = (const float*)d_in[11];
    const float* bak  = (const float*)d_in[12];

    float* out        = (float*)d_out;
    float* out_values = out;
    float* out_logits = out + NB;

    cudaFuncSetAttribute(gat_main, cudaFuncAttributeMaxDynamicSharedMemorySize,
                         SMF * (int)sizeof(float));

    precomp<<<17, 256>>>(Wdr, Wdk, asrc, adst, Wad, Wak, bad, bak);
    gat_main<<<NB, 256, SMF * sizeof(float)>>>(obs, Wdk, out_logits);
    critic_gemm<<<dim3(NB / 32, KSPLIT), 256>>>(Wc1);
    critic_final<<<NB / 8, 256>>>(bc1, Wc2, bc2, out_values);
}